// round 15
// baseline (speedup 1.0000x reference)
#include <cuda_runtime.h>
#include <cuda_fp16.h>
#include <math.h>
#include <stdint.h>

// ---------------------------------------------------------------------------
// SupPatchNCELoss — GB300 (sm_103a), round 14: fp16 HMMA + LDSM, 64x64 warp
// tiles, S2 via class-sum identity. (tcgen05 unavailable: harness PTX target
// is compute_103 without the 'a' feature set — legacy mma.sync only.)
//
// loss = mean_i [ log S1_i - (S2_i - cnt_i)*(1/T)/cnt_i ]
//   S1_i  = sum_{j!=i} exp((cos_ij - 1)/T)     (Gram pass, fused epilogue)
//   S2_i  = f_i . K[lab_i] - ||f_i||^2         (class sums, O(M*C))
//   cnt_i = 2*hist[lab_i] - 1
// ---------------------------------------------------------------------------

#define NPATCH 4096
#define MROWS  8192
#define CDIM   256
#define HSEG   128
#define INV_T  (1.0f / 0.07f)

#define NT 64
#define NPAIRS (NT * (NT + 1) / 2)    // 2080

#define BK 32                         // halves per k-stage
#define SKDH 40                       // smem row stride (halves): 80B rows
#define STAGE_B (128 * SKDH * 2)      // bytes per tile-stage: 10240

__device__ __half g_half[MROWS * CDIM];
__device__ int    g_lab[NPATCH];
__device__ int    g_hist[8];
__device__ float  g_S1p[NT][MROWS];
__device__ float  g_Kp[64 * 5 * 256];
__device__ float  g_K[5 * 256];
__device__ float  g_part[128];

// ---------------------------------------------------------------------------
__device__ __forceinline__ unsigned sptr(const void* p) {
    return (unsigned)__cvta_generic_to_shared(p);
}
__device__ __forceinline__ void mma_f16(float c[4], const unsigned a[4],
                                        const unsigned b[2]) {
    asm volatile(
        "mma.sync.aligned.m16n8k16.row.col.f32.f16.f16.f32 "
        "{%0,%1,%2,%3}, {%4,%5,%6,%7}, {%8,%9}, {%0,%1,%2,%3};\n"
        : "+f"(c[0]), "+f"(c[1]), "+f"(c[2]), "+f"(c[3])
        : "r"(a[0]), "r"(a[1]), "r"(a[2]), "r"(a[3]), "r"(b[0]), "r"(b[1]));
}
#define LDSM_X4(r0, r1, r2, r3, a) \
    asm volatile("ldmatrix.sync.aligned.m8n8.x4.shared.b16 {%0,%1,%2,%3}, [%4];" \
        : "=r"(r0), "=r"(r1), "=r"(r2), "=r"(r3) : "r"(a))
__device__ __forceinline__ void cpa16(unsigned smem, const void* gp) {
    asm volatile("cp.async.cg.shared.global [%0], [%1], 16;\n"
                 :: "r"(smem), "l"(gp));
}
#define CP_COMMIT() asm volatile("cp.async.commit_group;\n" ::: "memory")
#define CP_WAIT(n)  asm volatile("cp.async.wait_group %0;\n" :: "n"(n) : "memory")

// ---------------------------------------------------------------------------
// 1) labels + histogram
// ---------------------------------------------------------------------------
__global__ void labels_kernel(const int* __restrict__ seg,
                              const int* __restrict__ coords,
                              const int* __restrict__ crw,
                              const int* __restrict__ crh,
                              const int* __restrict__ crd) {
    __shared__ int sh_hist[8];
    int t = threadIdx.x;
    if (t < 8) sh_hist[t] = 0;
    __syncthreads();
    int cw = *crw, ch = *crh, cd = *crd;
    for (int p = t; p < NPATCH; p += blockDim.x) {
        int cx = coords[p * 3 + 0];
        int cy = coords[p * 3 + 1];
        int cz = coords[p * 3 + 2];
        int ix = (cx * HSEG) / cw;
        int iy = (cy * HSEG) / ch;
        int iz = (cz * HSEG) / cd;
        int l = seg[(ix * HSEG + iy) * HSEG + iz];
        g_lab[p] = l;
        atomicAdd(&sh_hist[l & 7], 1);
    }
    __syncthreads();
    if (t < 8) g_hist[t] = sh_hist[t];
}

// ---------------------------------------------------------------------------
// 2) row-normalize -> fp16
// ---------------------------------------------------------------------------
__global__ void normalize_kernel(const float* __restrict__ f) {
    int warp = (blockIdx.x * blockDim.x + threadIdx.x) >> 5;
    int lane = threadIdx.x & 31;
    if (warp >= MROWS) return;
    const float4* src = (const float4*)(f + (size_t)warp * CDIM);
    float4 v0 = src[lane];
    float4 v1 = src[lane + 32];
    float ss = v0.x * v0.x + v0.y * v0.y + v0.z * v0.z + v0.w * v0.w
             + v1.x * v1.x + v1.y * v1.y + v1.z * v1.z + v1.w * v1.w;
    #pragma unroll
    for (int o = 16; o > 0; o >>= 1)
        ss += __shfl_xor_sync(0xffffffffu, ss, o);
    float inv = rsqrtf(fmaxf(ss, 1e-24f));
    __half2* dst = (__half2*)(g_half + (size_t)warp * CDIM);
    dst[lane * 2 + 0]      = __floats2half2_rn(v0.x * inv, v0.y * inv);
    dst[lane * 2 + 1]      = __floats2half2_rn(v0.z * inv, v0.w * inv);
    dst[64 + lane * 2 + 0] = __floats2half2_rn(v1.x * inv, v1.y * inv);
    dst[64 + lane * 2 + 1] = __floats2half2_rn(v1.z * inv, v1.w * inv);
}

// ---------------------------------------------------------------------------
// 3a) class sums: 64 blocks x 256 threads (thread = dim), then combine
// ---------------------------------------------------------------------------
__global__ void ksum_kernel() {
    int t = threadIdx.x;
    int r0 = blockIdx.x * 128;
    float a0 = 0.f, a1 = 0.f, a2 = 0.f, a3 = 0.f, a4 = 0.f;
    for (int r = 0; r < 128; r++) {
        int row = r0 + r;
        float v = __half2float(g_half[(size_t)row * CDIM + t]);
        int lab = g_lab[row & (NPATCH - 1)];
        a0 += (lab == 0) ? v : 0.f;
        a1 += (lab == 1) ? v : 0.f;
        a2 += (lab == 2) ? v : 0.f;
        a3 += (lab == 3) ? v : 0.f;
        a4 += (lab == 4) ? v : 0.f;
    }
    int b = blockIdx.x;
    g_Kp[(b * 5 + 0) * 256 + t] = a0;
    g_Kp[(b * 5 + 1) * 256 + t] = a1;
    g_Kp[(b * 5 + 2) * 256 + t] = a2;
    g_Kp[(b * 5 + 3) * 256 + t] = a3;
    g_Kp[(b * 5 + 4) * 256 + t] = a4;
}

__global__ void kcombine_kernel() {
    int cls = blockIdx.x, t = threadIdx.x;
    float s = 0.f;
    for (int b = 0; b < 64; b++)
        s += g_Kp[(b * 5 + cls) * 256 + t];
    g_K[cls * 256 + t] = s;
}

// ---------------------------------------------------------------------------
// 3b) symmetric Gram + fused S1 epilogue. 2080 blocks x 128 threads,
//     4 warps (wy,wx in {0,1}), warp tile 64x64, LDSM fragments,
//     double-buffered cp.async, BK=32 halves.
// ---------------------------------------------------------------------------
__global__ __launch_bounds__(128, 2) void gram_kernel() {
    extern __shared__ __half dynh[];
    unsigned smem0 = sptr(dynh);
    unsigned Ab[2] = { smem0, smem0 + STAGE_B };
    unsigned Bb[2] = { smem0 + 2 * STAGE_B, smem0 + 3 * STAGE_B };

    __shared__ float sR[2][128], sC[2][128];

    int b = blockIdx.x;
    int I = 0;
    while (b >= NT - I) { b -= NT - I; I++; }
    int J = I + b;
    int rowBase = I * 128, colBase = J * 128;

    int tid = threadIdx.x;
    int lane = tid & 31, w = tid >> 5;
    int wy = w >> 1, wx = w & 1;
    int g = lane >> 2, t4 = lane & 3;

    // LDSM per-lane address parts: matrix m = lane>>3
    int m_ = lane >> 3;
    int rowp = (m_ & 1) * 8 + (lane & 7);
    int colp = (m_ >> 1) * 8;                 // halves

    // stage-load coords: 4 x 16B chunks per tile per thread
    int lrow[4], lhoff[4];
    #pragma unroll
    for (int i = 0; i < 4; i++) {
        int idx = tid + i * 128;              // 0..511
        lrow[i] = idx >> 2;                   // 0..127
        lhoff[i] = (idx & 3) * 8;             // 0,8,16,24 halves
    }

    // prefetch stage 0
    #pragma unroll
    for (int i = 0; i < 4; i++) {
        unsigned off = (unsigned)(lrow[i] * (SKDH * 2) + lhoff[i] * 2);
        cpa16(Ab[0] + off, g_half + (size_t)(rowBase + lrow[i]) * CDIM + lhoff[i]);
        cpa16(Bb[0] + off, g_half + (size_t)(colBase + lrow[i]) * CDIM + lhoff[i]);
    }
    CP_COMMIT();

    float acc[4][8][4];
    #pragma unroll
    for (int mi = 0; mi < 4; mi++)
        #pragma unroll
        for (int ni = 0; ni < 8; ni++)
            #pragma unroll
            for (int q = 0; q < 4; q++) acc[mi][ni][q] = 0.0f;

    #pragma unroll 1
    for (int kbi = 0; kbi < CDIM / BK; kbi++) {
        int cur = kbi & 1;
        if (kbi < CDIM / BK - 1) {
            int kb = (kbi + 1) * BK;
            #pragma unroll
            for (int i = 0; i < 4; i++) {
                unsigned off = (unsigned)(lrow[i] * (SKDH * 2) + lhoff[i] * 2);
                cpa16(Ab[cur ^ 1] + off,
                      g_half + (size_t)(rowBase + lrow[i]) * CDIM + kb + lhoff[i]);
                cpa16(Bb[cur ^ 1] + off,
                      g_half + (size_t)(colBase + lrow[i]) * CDIM + kb + lhoff[i]);
            }
            CP_COMMIT();
            CP_WAIT(1);
        } else {
            CP_WAIT(0);
        }
        __syncthreads();

        #pragma unroll
        for (int kk = 0; kk < BK; kk += 16) {
            unsigned af[4][4], bf[8][2];
            #pragma unroll
            for (int mi = 0; mi < 4; mi++) {
                unsigned a = Ab[cur]
                    + (unsigned)((wy * 64 + mi * 16 + rowp) * (SKDH * 2)
                                 + (kk + colp) * 2);
                LDSM_X4(af[mi][0], af[mi][1], af[mi][2], af[mi][3], a);
            }
            #pragma unroll
            for (int nb = 0; nb < 4; nb++) {
                unsigned a = Bb[cur]
                    + (unsigned)((wx * 64 + nb * 16 + rowp) * (SKDH * 2)
                                 + (kk + colp) * 2);
                LDSM_X4(bf[2 * nb][0], bf[2 * nb + 1][0],
                        bf[2 * nb][1], bf[2 * nb + 1][1], a);
            }
            #pragma unroll
            for (int mi = 0; mi < 4; mi++)
                #pragma unroll
                for (int ni = 0; ni < 8; ni++)
                    mma_f16(acc[mi][ni], af[mi], bf[ni]);
        }
        __syncthreads();
    }

    // ---- fused epilogue: exp row sums + col sums (no labels) ----
    bool diag = (I == J);
    float cs[8][2];
    #pragma unroll
    for (int ni = 0; ni < 8; ni++) { cs[ni][0] = 0.f; cs[ni][1] = 0.f; }

    #pragma unroll
    for (int mi = 0; mi < 4; mi++) {
        float r0 = 0.f, r1 = 0.f;
        #pragma unroll
        for (int ni = 0; ni < 8; ni++) {
            #pragma unroll
            for (int q = 0; q < 4; q++) {
                float v = acc[mi][ni][q];
                float e = __expf((v - 1.0f) * INV_T);
                if (diag) {
                    int lr = wy * 64 + mi * 16 + ((q & 2) ? 8 : 0) + g;
                    int lc = wx * 64 + ni * 8 + 2 * t4 + (q & 1);
                    if (lr == lc) e = 0.f;
                }
                if (q & 2) r1 += e; else r0 += e;
                cs[ni][q & 1] += e;
            }
        }
        #pragma unroll
        for (int h = 0; h < 2; h++) {
            float v = h ? r1 : r0;
            v += __shfl_xor_sync(0xffffffffu, v, 1);
            v += __shfl_xor_sync(0xffffffffu, v, 2);
            if (t4 == 0)
                sR[wx][wy * 64 + mi * 16 + h * 8 + g] = v;
        }
    }

    #pragma unroll
    for (int ni = 0; ni < 8; ni++) {
        #pragma unroll
        for (int h = 0; h < 2; h++) {
            float v = cs[ni][h];
            v += __shfl_xor_sync(0xffffffffu, v, 4);
            v += __shfl_xor_sync(0xffffffffu, v, 8);
            v += __shfl_xor_sync(0xffffffffu, v, 16);
            if (g == 0)
                sC[wy][wx * 64 + ni * 8 + 2 * t4 + h] = v;
        }
    }
    __syncthreads();

    // deterministic partial writes: slot = other tile index
    {
        int r = tid;
        g_S1p[J][rowBase + r] = sR[0][r] + sR[1][r];
        if (I < J)
            g_S1p[I][colBase + r] = sC[0][r] + sC[1][r];
    }
}

// ---------------------------------------------------------------------------
// 4) final: S1 slot-sum + S2 = f.K[lab] - ||f||^2 -> loss partials
// ---------------------------------------------------------------------------
__global__ void final1_kernel() {
    __shared__ float pS1[4][64], pDot[4][64], pSelf[4][64];
    __shared__ float sh[64];
    int r6 = threadIdx.x & 63, part = threadIdx.x >> 6;
    int row = blockIdx.x * 64 + r6;
    int lab = g_lab[row & (NPATCH - 1)];

    float S1 = 0.f;
    #pragma unroll
    for (int sidx = part * 16; sidx < part * 16 + 16; sidx++)
        S1 += g_S1p[sidx][row];

    const __half2* f2 = (const __half2*)(g_half + (size_t)row * CDIM);
    const float* Kc = g_K + lab * 256;
    float dot = 0.f, self = 0.f;
    #pragma unroll
    for (int d = part * 32; d < part * 32 + 32; d++) {
        float2 v = __half22float2(f2[d]);
        dot  += v.x * Kc[2 * d] + v.y * Kc[2 * d + 1];
        self += v.x * v.x + v.y * v.y;
    }
    pS1[part][r6] = S1;
    pDot[part][r6] = dot;
    pSelf[part][r6] = self;
    __syncthreads();
    if (part == 0) {
        float fS1 = pS1[0][r6] + pS1[1][r6] + pS1[2][r6] + pS1[3][r6];
        float fD  = pDot[0][r6] + pDot[1][r6] + pDot[2][r6] + pDot[3][r6];
        float fSf = pSelf[0][r6] + pSelf[1][r6] + pSelf[2][r6] + pSelf[3][r6];
        float cnt = (float)(2 * g_hist[lab & 7] - 1);
        float S2 = fD - fSf;
        sh[r6] = logf(fS1) - (S2 - cnt) * (INV_T / cnt);
    }
    __syncthreads();
    if (threadIdx.x < 32) {
        float v = sh[threadIdx.x] + sh[threadIdx.x + 32];
        #pragma unroll
        for (int o = 16; o > 0; o >>= 1)
            v += __shfl_xor_sync(0xffffffffu, v, o);
        if (threadIdx.x == 0) g_part[blockIdx.x] = v;
    }
}

__global__ void final2_kernel(float* __restrict__ out) {
    __shared__ float sh[128];
    sh[threadIdx.x] = g_part[threadIdx.x];
    __syncthreads();
    for (int o = 64; o > 0; o >>= 1) {
        if (threadIdx.x < o) sh[threadIdx.x] += sh[threadIdx.x + o];
        __syncthreads();
    }
    if (threadIdx.x == 0) out[0] = sh[0] / (float)MROWS;
}

// ---------------------------------------------------------------------------
extern "C" void kernel_launch(void* const* d_in, const int* in_sizes, int n_in,
                              void* d_out, int out_size) {
    const float* features = (const float*)d_in[0];
    const int*   seg      = (const int*)d_in[1];
    const int*   coords   = (const int*)d_in[2];
    const int*   crw      = (const int*)d_in[3];
    const int*   crh      = (const int*)d_in[4];
    const int*   crd      = (const int*)d_in[5];
    float* out = (float*)d_out;

    const int dynBytes = 4 * STAGE_B;   // 40960 < 48K default

    labels_kernel<<<1, 256>>>(seg, coords, crw, crh, crd);
    normalize_kernel<<<MROWS / 8, 256>>>(features);
    ksum_kernel<<<64, 256>>>();
    kcombine_kernel<<<5, 256>>>();
    gram_kernel<<<NPAIRS, 128, dynBytes>>>();
    final1_kernel<<<128, 256>>>();
    final2_kernel<<<1, 128>>>(out);
}

// round 16
// speedup vs baseline: 1.1511x; 1.1511x over previous
#include <cuda_runtime.h>
#include <cuda_fp16.h>
#include <cuda_bf16.h>
#include <math.h>
#include <stdint.h>

// ---------------------------------------------------------------------------
// SupPatchNCELoss — GB300 (sm_103a), round 15: R11 config + ldmatrix loads
//
// loss = mean_i [ log S1_i - (S2_i - cnt_i) * (1/T) / cnt_i ]
//   S1_i = sum_{j!=i} exp((cos_ij - 1)/T)
//   S2_i = sum_{j!=i, lab_j==lab_i} cos_ij
//   cnt_i = 2*hist[lab_i] - 1
//
// R15 vs R11 (96.7us best): fragment loads via ldmatrix.x4 (LDSM) instead of
// 24 scalar LDS.32 per warp per kk-step — 4x fewer issue slots, same bytes.
// Everything else (tiles, occupancy, epilogue, partials) identical to R11.
// LDSM lane mapping proven correct in R14; R14's 64x64-tile occupancy loss
// reverted.
// ---------------------------------------------------------------------------

#define NPATCH 4096
#define MROWS  8192
#define CDIM   256
#define HSEG   128
#define INV_T  (1.0f / 0.07f)

#define NT 64                        // 8192/128 tiles per dim
#define NPAIRS (NT * (NT + 1) / 2)   // 2080

#define BK 32                        // k-chunk (halves) per stage
#define SKDH 40                      // smem k-stride in halves (conflict-free)
#define STAGE_H (128 * SKDH)         // halves per tile-buffer

__device__ __half g_half[MROWS * CDIM];      // fp16 normalized features (4 MB)
__device__ int    g_lab[NPATCH];
__device__ int    g_hist[8];
__device__ float  g_S1p[NT][MROWS];
__device__ float  g_S2p[NT][MROWS];
__device__ float  g_part[128];

// ---------------------------------------------------------------------------
__device__ __forceinline__ unsigned sptr(const void* p) {
    return (unsigned)__cvta_generic_to_shared(p);
}
__device__ __forceinline__ void mma_f16(float c[4], const unsigned a[4],
                                        const unsigned b[2]) {
    asm volatile(
        "mma.sync.aligned.m16n8k16.row.col.f32.f16.f16.f32 "
        "{%0,%1,%2,%3}, {%4,%5,%6,%7}, {%8,%9}, {%0,%1,%2,%3};\n"
        : "+f"(c[0]), "+f"(c[1]), "+f"(c[2]), "+f"(c[3])
        : "r"(a[0]), "r"(a[1]), "r"(a[2]), "r"(a[3]), "r"(b[0]), "r"(b[1]));
}
#define LDSM_X4(r0, r1, r2, r3, a) \
    asm volatile("ldmatrix.sync.aligned.m8n8.x4.shared.b16 {%0,%1,%2,%3}, [%4];" \
        : "=r"(r0), "=r"(r1), "=r"(r2), "=r"(r3) : "r"(a))

__device__ __forceinline__ void cpa16(unsigned smem, const void* gp) {
    asm volatile("cp.async.cg.shared.global [%0], [%1], 16;\n"
                 :: "r"(smem), "l"(gp));
}
#define CP_COMMIT() asm volatile("cp.async.commit_group;\n" ::: "memory")
#define CP_WAIT(n)  asm volatile("cp.async.wait_group %0;\n" :: "n"(n) : "memory")

// ---------------------------------------------------------------------------
// 1) labels + histogram (single block)
// ---------------------------------------------------------------------------
__global__ void labels_kernel(const int* __restrict__ seg,
                              const int* __restrict__ coords,
                              const int* __restrict__ crw,
                              const int* __restrict__ crh,
                              const int* __restrict__ crd) {
    __shared__ int sh_hist[8];
    int t = threadIdx.x;
    if (t < 8) sh_hist[t] = 0;
    __syncthreads();
    int cw = *crw, ch = *crh, cd = *crd;
    for (int p = t; p < NPATCH; p += blockDim.x) {
        int cx = coords[p * 3 + 0];
        int cy = coords[p * 3 + 1];
        int cz = coords[p * 3 + 2];
        int ix = (cx * HSEG) / cw;
        int iy = (cy * HSEG) / ch;
        int iz = (cz * HSEG) / cd;
        int l = seg[(ix * HSEG + iy) * HSEG + iz];
        g_lab[p] = l;
        atomicAdd(&sh_hist[l & 7], 1);
    }
    __syncthreads();
    if (t < 8) g_hist[t] = sh_hist[t];
}

// ---------------------------------------------------------------------------
// 2) row-normalize -> fp16: one warp per row
// ---------------------------------------------------------------------------
__global__ void normalize_kernel(const float* __restrict__ f) {
    int warp = (blockIdx.x * blockDim.x + threadIdx.x) >> 5;
    int lane = threadIdx.x & 31;
    if (warp >= MROWS) return;
    const float4* src = (const float4*)(f + (size_t)warp * CDIM);
    float4 v0 = src[lane];
    float4 v1 = src[lane + 32];
    float ss = v0.x * v0.x + v0.y * v0.y + v0.z * v0.z + v0.w * v0.w
             + v1.x * v1.x + v1.y * v1.y + v1.z * v1.z + v1.w * v1.w;
    #pragma unroll
    for (int o = 16; o > 0; o >>= 1)
        ss += __shfl_xor_sync(0xffffffffu, ss, o);
    float inv = rsqrtf(fmaxf(ss, 1e-24f));
    __half2* dst = (__half2*)(g_half + (size_t)warp * CDIM);
    dst[lane * 2 + 0]      = __floats2half2_rn(v0.x * inv, v0.y * inv);
    dst[lane * 2 + 1]      = __floats2half2_rn(v0.z * inv, v0.w * inv);
    dst[64 + lane * 2 + 0] = __floats2half2_rn(v1.x * inv, v1.y * inv);
    dst[64 + lane * 2 + 1] = __floats2half2_rn(v1.z * inv, v1.w * inv);
}

// ---------------------------------------------------------------------------
// 3) symmetric Gram + fused epilogue, fp16 HMMA + LDSM, double-buffered
//    cp.async. 2080 blocks, 256 threads = 8 warps (wy in {0,1}, wx in {0..3}),
//    warp tile 64x32, block tile 128x128, K staged in chunks of 32 halves.
// ---------------------------------------------------------------------------
__global__ __launch_bounds__(256, 2) void gram_kernel() {
    extern __shared__ __half dynh[];
    unsigned smem0 = sptr(dynh);
    unsigned Ab[2] = { smem0, smem0 + STAGE_H * 2 };
    unsigned Bb[2] = { smem0 + 4 * STAGE_H, smem0 + 6 * STAGE_H };

    __shared__ int   labR[128], labC[128];
    __shared__ float sR1[4][128], sR2[4][128];
    __shared__ float sC1[2][128], sC2[2][128];

    // linear block -> (I, J) with I <= J
    int b = blockIdx.x;
    int I = 0;
    while (b >= NT - I) { b -= NT - I; I++; }
    int J = I + b;
    int rowBase = I * 128, colBase = J * 128;

    int tid  = threadIdx.x;
    int lane = tid & 31, w = tid >> 5;
    int wy = w >> 2, wx = w & 3;
    int g = lane >> 2, t4 = lane & 3;

    if (tid < 128) labR[tid] = g_lab[(rowBase + tid) & (NPATCH - 1)];
    else           labC[tid - 128] = g_lab[(colBase + tid - 128) & (NPATCH - 1)];

    // LDSM per-lane address components: matrix idx m = lane>>3
    int m_   = lane >> 3;
    int rowp = (m_ & 1) * 8 + (lane & 7);     // row within 16-row group
    int colp = (m_ >> 1) * 8;                 // half-offset within 16-k group

    // stage-load coords: 2 x 16B chunks per tile per thread
    int lrow[2], lhoff[2];
    #pragma unroll
    for (int i = 0; i < 2; i++) {
        int idx = tid + i * 256;          // 0..511
        lrow[i]  = idx >> 2;              // 0..127
        lhoff[i] = (idx & 3) * 8;         // 0,8,16,24 halves
    }

    // prefetch stage 0
    #pragma unroll
    for (int i = 0; i < 2; i++) {
        unsigned off = (unsigned)(lrow[i] * (SKDH * 2) + lhoff[i] * 2);
        cpa16(Ab[0] + off, g_half + (size_t)(rowBase + lrow[i]) * CDIM + lhoff[i]);
        cpa16(Bb[0] + off, g_half + (size_t)(colBase + lrow[i]) * CDIM + lhoff[i]);
    }
    CP_COMMIT();

    float acc[4][4][4];
    #pragma unroll
    for (int mi = 0; mi < 4; mi++)
        #pragma unroll
        for (int ni = 0; ni < 4; ni++)
            #pragma unroll
            for (int q = 0; q < 4; q++) acc[mi][ni][q] = 0.0f;

    #pragma unroll 1
    for (int kbi = 0; kbi < CDIM / BK; kbi++) {
        int cur = kbi & 1;
        if (kbi < CDIM / BK - 1) {
            int kb = (kbi + 1) * BK;
            #pragma unroll
            for (int i = 0; i < 2; i++) {
                unsigned off = (unsigned)(lrow[i] * (SKDH * 2) + lhoff[i] * 2);
                cpa16(Ab[cur ^ 1] + off,
                      g_half + (size_t)(rowBase + lrow[i]) * CDIM + kb + lhoff[i]);
                cpa16(Bb[cur ^ 1] + off,
                      g_half + (size_t)(colBase + lrow[i]) * CDIM + kb + lhoff[i]);
            }
            CP_COMMIT();
            CP_WAIT(1);
        } else {
            CP_WAIT(0);
        }
        __syncthreads();

        #pragma unroll
        for (int kk = 0; kk < BK; kk += 16) {
            unsigned af[4][4], bf[4][2];
            // A fragments: 4 x LDSM_X4 (rows wy*64+mi*16, k-chunk kk)
            #pragma unroll
            for (int mi = 0; mi < 4; mi++) {
                unsigned a = Ab[cur]
                    + (unsigned)((wy * 64 + mi * 16 + rowp) * (SKDH * 2)
                                 + (kk + colp) * 2);
                LDSM_X4(af[mi][0], af[mi][1], af[mi][2], af[mi][3], a);
            }
            // B fragments: 2 x LDSM_X4 cover 32 cols (4 n8 groups)
            #pragma unroll
            for (int nb = 0; nb < 2; nb++) {
                unsigned a = Bb[cur]
                    + (unsigned)((wx * 32 + nb * 16 + rowp) * (SKDH * 2)
                                 + (kk + colp) * 2);
                LDSM_X4(bf[2 * nb][0], bf[2 * nb + 1][0],
                        bf[2 * nb][1], bf[2 * nb + 1][1], a);
            }
            #pragma unroll
            for (int mi = 0; mi < 4; mi++)
                #pragma unroll
                for (int ni = 0; ni < 4; ni++)
                    mma_f16(acc[mi][ni], af[mi], bf[ni]);
        }
        __syncthreads();
    }

    // ---- fused epilogue: exp-sum + label-masked cos-sum, both sides ----
    float cs1[4][2], cs2[4][2];
    #pragma unroll
    for (int ni = 0; ni < 4; ni++) {
        cs1[ni][0] = 0.f; cs1[ni][1] = 0.f;
        cs2[ni][0] = 0.f; cs2[ni][1] = 0.f;
    }
    bool diag = (I == J);

    #pragma unroll
    for (int mi = 0; mi < 4; mi++) {
        float rs1[2] = {0.f, 0.f}, rs2[2] = {0.f, 0.f};
        int lr0 = wy * 64 + mi * 16 + g;
        int lr1 = lr0 + 8;
        int labr0 = labR[lr0], labr1 = labR[lr1];
        #pragma unroll
        for (int ni = 0; ni < 4; ni++) {
            int lc0 = wx * 32 + ni * 8 + 2 * t4;
            int lc1 = lc0 + 1;
            int labc0 = labC[lc0], labc1 = labC[lc1];
            #pragma unroll
            for (int q = 0; q < 4; q++) {
                int lr = (q & 2) ? lr1 : lr0;
                int lc = (q & 1) ? lc1 : lc0;
                int lbr = (q & 2) ? labr1 : labr0;
                int lbc = (q & 1) ? labc1 : labc0;
                float v = acc[mi][ni][q];
                bool self = diag && (lr == lc);
                float e = __expf((v - 1.0f) * INV_T);
                if (!self) {
                    rs1[(q >> 1)] += e;
                    cs1[ni][(q & 1)] += e;
                    if (lbr == lbc) {
                        rs2[(q >> 1)] += v;
                        cs2[ni][(q & 1)] += v;
                    }
                }
            }
        }
        #pragma unroll
        for (int h = 0; h < 2; h++) {
            float v1 = rs1[h], v2 = rs2[h];
            v1 += __shfl_xor_sync(0xffffffffu, v1, 1);
            v1 += __shfl_xor_sync(0xffffffffu, v1, 2);
            v2 += __shfl_xor_sync(0xffffffffu, v2, 1);
            v2 += __shfl_xor_sync(0xffffffffu, v2, 2);
            if (t4 == 0) {
                int lr = wy * 64 + mi * 16 + h * 8 + g;
                sR1[wx][lr] = v1;
                sR2[wx][lr] = v2;
            }
        }
    }

    #pragma unroll
    for (int ni = 0; ni < 4; ni++) {
        #pragma unroll
        for (int h = 0; h < 2; h++) {
            float v1 = cs1[ni][h], v2 = cs2[ni][h];
            v1 += __shfl_xor_sync(0xffffffffu, v1, 4);
            v1 += __shfl_xor_sync(0xffffffffu, v1, 8);
            v1 += __shfl_xor_sync(0xffffffffu, v1, 16);
            v2 += __shfl_xor_sync(0xffffffffu, v2, 4);
            v2 += __shfl_xor_sync(0xffffffffu, v2, 8);
            v2 += __shfl_xor_sync(0xffffffffu, v2, 16);
            if (g == 0) {
                int lc = wx * 32 + ni * 8 + 2 * t4 + h;
                sC1[wy][lc] = v1;
                sC2[wy][lc] = v2;
            }
        }
    }
    __syncthreads();

    // deterministic partial writes: slot = other tile index
    if (tid < 128) {
        int r = tid;
        g_S1p[J][rowBase + r] = sR1[0][r] + sR1[1][r] + sR1[2][r] + sR1[3][r];
        g_S2p[J][rowBase + r] = sR2[0][r] + sR2[1][r] + sR2[2][r] + sR2[3][r];
    } else if (I < J) {
        int c = tid - 128;
        g_S1p[I][colBase + c] = sC1[0][c] + sC1[1][c];
        g_S2p[I][colBase + c] = sC2[0][c] + sC2[1][c];
    }
}

// ---------------------------------------------------------------------------
// 4) final reduction: 128 blocks x 256 threads; 64 rows/block, 4-way split
// ---------------------------------------------------------------------------
__global__ void final1_kernel() {
    __shared__ float p1[4][64], p2[4][64];
    __shared__ float sh[64];
    int r6   = threadIdx.x & 63;
    int part = threadIdx.x >> 6;
    int row  = blockIdx.x * 64 + r6;
    float S1 = 0.0f, S2 = 0.0f;
    #pragma unroll
    for (int s = part * 16; s < part * 16 + 16; s++) {
        S1 += g_S1p[s][row];
        S2 += g_S2p[s][row];
    }
    p1[part][r6] = S1;
    p2[part][r6] = S2;
    __syncthreads();
    if (part == 0) {
        float fS1 = p1[0][r6] + p1[1][r6] + p1[2][r6] + p1[3][r6];
        float fS2 = p2[0][r6] + p2[1][r6] + p2[2][r6] + p2[3][r6];
        int lb = g_lab[row & (NPATCH - 1)] & 7;
        float cnt = (float)(2 * g_hist[lb] - 1);
        sh[r6] = logf(fS1) - (fS2 - cnt) * (INV_T / cnt);
    }
    __syncthreads();
    if (threadIdx.x < 32) {
        float v = sh[threadIdx.x] + sh[threadIdx.x + 32];
        #pragma unroll
        for (int o = 16; o > 0; o >>= 1)
            v += __shfl_xor_sync(0xffffffffu, v, o);
        if (threadIdx.x == 0) g_part[blockIdx.x] = v;
    }
}

__global__ void final2_kernel(float* __restrict__ out) {
    __shared__ float sh[128];
    sh[threadIdx.x] = g_part[threadIdx.x];
    __syncthreads();
    for (int o = 64; o > 0; o >>= 1) {
        if (threadIdx.x < o) sh[threadIdx.x] += sh[threadIdx.x + o];
        __syncthreads();
    }
    if (threadIdx.x == 0) out[0] = sh[0] / (float)MROWS;
}

// ---------------------------------------------------------------------------
extern "C" void kernel_launch(void* const* d_in, const int* in_sizes, int n_in,
                              void* d_out, int out_size) {
    const float* features = (const float*)d_in[0];
    const int*   seg      = (const int*)d_in[1];
    const int*   coords   = (const int*)d_in[2];
    const int*   crw      = (const int*)d_in[3];
    const int*   crh      = (const int*)d_in[4];
    const int*   crd      = (const int*)d_in[5];
    float* out = (float*)d_out;

    const int dynBytes = 8 * STAGE_H;   // 4 buffers x 10240 B = 40960

    labels_kernel<<<1, 256>>>(seg, coords, crw, crh, crd);
    normalize_kernel<<<MROWS / 8, 256>>>(features);
    gram_kernel<<<NPAIRS, 256, dynBytes>>>();
    final1_kernel<<<128, 256>>>();
    final2_kernel<<<1, 128>>>(out);
}